// round 11
// baseline (speedup 1.0000x reference)
#include <cuda_runtime.h>
#include <cuda_fp16.h>
#include <cstdint>

// ===================== problem constants =====================
#define BATCH 1024
#define EMB 512
#define NCLS 200000
#define NT 128                   // classes per CTA tile
#define NTILES 1563              // ceil(NCLS / NT)
#define TILE_BYTES 131072        // 128 rows x 512 k x 2B (fp16 tile)
#define CHUNK_BYTES 16384        // 128 rows x 64 k fp16 (pipeline chunk)
#define NBUF 4
#define NCHUNKS 64               // 8 m-tiles x 8 chunks
#define SCALE_S 64.0f
#define COS_M 0.877582561890373f
#define SIN_M 0.479425538604203f
#define K_LOG2E 92.332482616893657f   // 64 * log2(e)

// ===================== device scratch =====================
__device__ __align__(1024) unsigned char g_A[8 * TILE_BYTES];  // 1 MB fp16 tiled embeddings
__device__ float g_rowsum[BATCH];
__device__ float g_target[BATCH];
__device__ int   g_labels[BATCH];

#define DEVINL __device__ __forceinline__

// ===================== PTX helpers =====================
DEVINL uint32_t smem_u32(const void* p) {
    uint32_t a;
    asm("{ .reg .u64 t; cvta.to.shared.u64 t, %1; cvt.u32.u64 %0, t; }" : "=r"(a) : "l"(p));
    return a;
}

#define MBARRIER_INIT(addr, cnt) \
    asm volatile("mbarrier.init.shared.b64 [%0], %1;" :: "r"((uint32_t)(addr)), "r"((uint32_t)(cnt)) : "memory")

#define MBARRIER_EXPECT_TX(addr, bytes) \
    asm volatile("mbarrier.arrive.expect_tx.shared.b64 _, [%0], %1;" :: "r"((uint32_t)(addr)), "r"((uint32_t)(bytes)) : "memory")

#define MBARRIER_ARRIVE(addr) \
    asm volatile("mbarrier.arrive.shared.b64 _, [%0];" :: "r"((uint32_t)(addr)) : "memory")

#define MBARRIER_WAIT_PARITY(addr, parity) do {                                   \
    asm volatile(                                                                 \
        "{\n\t.reg .pred P1;\n\t"                                                 \
        "WAIT_LOOP_%=:\n\t"                                                       \
        "mbarrier.try_wait.parity.acquire.cta.shared::cta.b64 P1, [%0], %1, 0x989680;\n\t" \
        "@P1 bra.uni WAIT_DONE_%=;\n\t"                                           \
        "bra.uni WAIT_LOOP_%=;\n\t"                                               \
        "WAIT_DONE_%=:\n\t}"                                                      \
        :: "r"((uint32_t)(addr)), "r"((uint32_t)(parity)) : "memory");            \
} while (0)

#define MBAR_INVAL(addr) \
    asm volatile("mbarrier.inval.shared.b64 [%0];" :: "r"((uint32_t)(addr)) : "memory")

#define BULK_G2S(dst_smem, src_gmem, bytes, mbar)                                                   \
    asm volatile("cp.async.bulk.shared::cluster.global.mbarrier::complete_tx::bytes [%0], [%1], %2, [%3];" \
        :: "r"((uint32_t)(dst_smem)), "l"(src_gmem), "r"((uint32_t)(bytes)), "r"((uint32_t)(mbar)) : "memory")

DEVINL void ldsm_x4(uint32_t* r, uint32_t addr) {
    asm volatile("ldmatrix.sync.aligned.m8n8.x4.shared.b16 {%0,%1,%2,%3}, [%4];"
                 : "=r"(r[0]), "=r"(r[1]), "=r"(r[2]), "=r"(r[3]) : "r"(addr));
}

// fp16 MMA with fp16 accumulate: D(2 regs) = A(4) * B(2) + C(2)
DEVINL void mma_h(uint32_t* c, const uint32_t* a, uint32_t b0, uint32_t b1) {
    asm volatile(
        "mma.sync.aligned.m16n8k16.row.col.f16.f16.f16.f16 "
        "{%0,%1}, {%2,%3,%4,%5}, {%6,%7}, {%0,%1};"
        : "+r"(c[0]), "+r"(c[1])
        : "r"(a[0]), "r"(a[1]), "r"(a[2]), "r"(a[3]), "r"(b0), "r"(b1));
}

DEVINL uint32_t hadd2(uint32_t x, uint32_t y) {
    uint32_t r;
    asm("add.f16x2 %0, %1, %2;" : "=r"(r) : "r"(x), "r"(y));
    return r;
}

DEVINL float ex2f(float x) {
    float r;
    asm("ex2.approx.f32 %0, %1;" : "=f"(r) : "f"(x));
    return r;
}

// fp16 element (row 0..127, k 0..511) inside a 128-row tiled region:
// [k/64 superblock: 16KB][row/8 group: 1KB][SW128 atom: 8 rows x 128B]
DEVINL uint32_t sw_addr(uint32_t base, int row, int k) {
    return base + (uint32_t)(((k >> 6) << 14) + ((row >> 3) << 10) + ((row & 7) << 7)
                             + (((k & 63) << 1) ^ ((row & 7) << 4)));
}

// fp16 element (row 0..127, k 0..63) inside one 16KB chunk buffer
DEVINL uint32_t chunk_addr(uint32_t base, int row, int k) {
    return base + (uint32_t)(((row >> 3) << 10) + ((row & 7) << 7)
                             + ((k << 1) ^ ((row & 7) << 4)));
}

// gmem scratch side (A): element (rr 0..127, k 0..511) in a 128x512 tile
DEVINL uint32_t tile_elem_off(int rr, int k) {
    return (uint32_t)(((k >> 6) << 14) + ((rr >> 3) << 10) + ((rr & 7) << 7)
                      + (((k & 63) << 1) ^ ((rr & 7) << 4)));
}

// ===================== prep =====================
DEVINL float dot4(float4 v) { return v.x * v.x + v.y * v.y + v.z * v.z + v.w * v.w; }
DEVINL uint32_t pk2h(float a, float b) {
    __half2 h = __floats2half2_rn(a, b);
    return *reinterpret_cast<uint32_t*>(&h);
}

__global__ void k_prep_a(const float* __restrict__ emb) {
    int r = blockIdx.x * 8 + (threadIdx.x >> 5);
    int lane = threadIdx.x & 31;
    unsigned char* base = g_A + (size_t)(r >> 7) * TILE_BYTES;
    int rr = r & 127;
    const float4* s = reinterpret_cast<const float4*>(emb + (size_t)r * EMB);
    float4 x0 = s[2 * lane], x1 = s[2 * lane + 1];
    float4 x2 = s[64 + 2 * lane], x3 = s[65 + 2 * lane];
    float ss = dot4(x0) + dot4(x1) + dot4(x2) + dot4(x3);
    #pragma unroll
    for (int o = 16; o; o >>= 1) ss += __shfl_xor_sync(0xFFFFFFFFu, ss, o);
    float inv = 1.0f / fmaxf(sqrtf(ss), 1e-12f);
    uint4 a, b;
    a.x = pk2h(x0.x * inv, x0.y * inv); a.y = pk2h(x0.z * inv, x0.w * inv);
    a.z = pk2h(x1.x * inv, x1.y * inv); a.w = pk2h(x1.z * inv, x1.w * inv);
    b.x = pk2h(x2.x * inv, x2.y * inv); b.y = pk2h(x2.z * inv, x2.w * inv);
    b.z = pk2h(x3.x * inv, x3.y * inv); b.w = pk2h(x3.z * inv, x3.w * inv);
    *reinterpret_cast<uint4*>(base + tile_elem_off(rr, 8 * lane)) = a;
    *reinterpret_cast<uint4*>(base + tile_elem_off(rr, 256 + 8 * lane)) = b;
}

// labels: detect int64 vs int32 (odd 32-bit words all zero => int64), zero rowsum
__global__ void k_labels(const int* __restrict__ lw) {
    __shared__ int s64;
    int tid = threadIdx.x;
    if (tid == 0) s64 = 1;
    __syncthreads();
    if (tid < 64) {
        if (lw[2 * tid + 1] != 0) atomicExch(&s64, 0);
    }
    __syncthreads();
    int is64 = s64;
    for (int i = tid; i < BATCH; i += 256) {
        g_labels[i] = is64 ? lw[2 * i] : lw[i];
        g_rowsum[i] = 0.0f;
    }
}

// exact fp32 target logit per row: margined, added to rowsum (GEMM skips label col)
__global__ void k_fix(const float* __restrict__ emb, const float* __restrict__ w) {
    int wrp = (blockIdx.x * blockDim.x + threadIdx.x) >> 5;   // 0..1023
    int lane = threadIdx.x & 31;
    int lbl = g_labels[wrp];
    const float4* e4 = reinterpret_cast<const float4*>(emb + (size_t)wrp * EMB);
    const float4* w4 = reinterpret_cast<const float4*>(w + (size_t)lbl * EMB);
    float ee = 0.f, ww = 0.f, ew = 0.f;
    #pragma unroll
    for (int i = 0; i < 4; i++) {
        float4 a = e4[lane + 32 * i], b = w4[lane + 32 * i];
        ee += dot4(a); ww += dot4(b);
        ew += a.x * b.x + a.y * b.y + a.z * b.z + a.w * b.w;
    }
    #pragma unroll
    for (int o = 16; o; o >>= 1) {
        ee += __shfl_xor_sync(0xFFFFFFFFu, ee, o);
        ww += __shfl_xor_sync(0xFFFFFFFFu, ww, o);
        ew += __shfl_xor_sync(0xFFFFFFFFu, ew, o);
    }
    if (lane == 0) {
        float t = ew / (fmaxf(sqrtf(ee), 1e-12f) * fmaxf(sqrtf(ww), 1e-12f));
        t = fminf(fmaxf(t, -1.0f), 1.0f);
        t = fminf(fmaxf(t, -1.0f + 1e-7f), 1.0f - 1e-7f);
        float lg = (t * COS_M - sqrtf(fmaxf(1.0f - t * t, 0.0f)) * SIN_M) * SCALE_S;
        g_target[wrp] = lg;
        atomicAdd(&g_rowsum[wrp], __expf(lg - 64.0f));
    }
}

// ===================== fp16 GEMM + fused W-normalize + softmax-partial epilogue ===
// 288 threads: warps 0-7 compute (4 m-slices x 2 n-slices, warp tile 32x64),
// warp 8 = loader. B tile (128 classes x 512 k fp16 = 128 KB) SMEM-resident,
// built by the prologue (W read from DRAM exactly once, f32 -> normalized fp16).
// MMA accumulates in fp16; chunk sums accumulate via HADD2 (f16x2), converted
// to f32 only once per m-tile in the epilogue.
__global__ __launch_bounds__(288, 1) void k_gemm(const float* __restrict__ wraw) {
    extern __shared__ unsigned char smem[];
    uint32_t sb = smem_u32(smem);
    int tid = threadIdx.x, wid = tid >> 5, lane = tid & 31;

    const uint32_t MB_AL = sb + 32;    // full barriers [4]
    const uint32_t MB_AC = sb + 128;   // consumed barriers [4]
    const uint32_t A_OFF = 1024;       // 4 x 16KB chunk buffers
    const uint32_t B_OFF = 66560;      // 1024-aligned; +128KB => 197632 total

    if (tid == 0) {
        for (int i = 0; i < NBUF; i++) {
            MBARRIER_INIT(MB_AL + 16 * i, 1);
            MBARRIER_INIT(MB_AC + 16 * i, 8);
        }
    }
    __syncthreads();

    if (wid == 8) {
        if (lane == 0) {
            #pragma unroll
            for (int g = 0; g < NBUF; g++) {
                MBARRIER_EXPECT_TX(MB_AL + 16 * g, CHUNK_BYTES);
                BULK_G2S(sb + A_OFF + g * CHUNK_BYTES, g_A + (size_t)g * CHUNK_BYTES,
                         CHUNK_BYTES, MB_AL + 16 * g);
            }
            int ac_ph[NBUF] = {0, 0, 0, 0};
            for (int g = NBUF; g < NCHUNKS; g++) {
                int buf = g & (NBUF - 1);
                MBARRIER_WAIT_PARITY(MB_AC + 16 * buf, ac_ph[buf]); ac_ph[buf] ^= 1;
                MBARRIER_EXPECT_TX(MB_AL + 16 * buf, CHUNK_BYTES);
                BULK_G2S(sb + A_OFF + buf * CHUNK_BYTES, g_A + (size_t)g * CHUNK_BYTES,
                         CHUNK_BYTES, MB_AL + 16 * buf);
            }
        }
    } else {
        // ---- prologue: normalize this CTA's 128 W rows into SMEM B tile (fp16) ----
        #pragma unroll 1
        for (int rb = 0; rb < 4; rb++) {
            int r0 = wid * 16 + rb * 4;
            float4 x[4][4];
            #pragma unroll
            for (int rr = 0; rr < 4; rr++) {
                int c = blockIdx.x * NT + r0 + rr;
                if (c < NCLS) {
                    const float4* s = reinterpret_cast<const float4*>(wraw + (size_t)c * EMB);
                    #pragma unroll
                    for (int q = 0; q < 4; q++) x[rr][q] = s[q * 32 + lane];  // coalesced
                } else {
                    #pragma unroll
                    for (int q = 0; q < 4; q++) x[rr][q] = make_float4(0.f, 0.f, 0.f, 0.f);
                }
            }
            #pragma unroll
            for (int rr = 0; rr < 4; rr++) {
                float ss = dot4(x[rr][0]) + dot4(x[rr][1]) + dot4(x[rr][2]) + dot4(x[rr][3]);
                #pragma unroll
                for (int o = 16; o; o >>= 1) ss += __shfl_xor_sync(0xFFFFFFFFu, ss, o);
                float inv = 1.0f / fmaxf(sqrtf(ss), 1e-12f);
                #pragma unroll
                for (int q = 0; q < 4; q++) {
                    uint32_t lo = pk2h(x[rr][q].x * inv, x[rr][q].y * inv);
                    uint32_t hi = pk2h(x[rr][q].z * inv, x[rr][q].w * inv);
                    uint32_t addr = sw_addr(sb + B_OFF, r0 + rr, q * 128 + lane * 4);
                    asm volatile("st.shared.v2.b32 [%0], {%1, %2};" :: "r"(addr), "r"(lo), "r"(hi) : "memory");
                }
            }
        }
        asm volatile("bar.sync 1, 256;" ::: "memory");   // compute warps only

        // ---- main loop ----
        int wm = wid & 3, wn = wid >> 2;                 // 4 m-slices x 2 n-slices
        int grp = lane >> 3, r8 = lane & 7;
        int a_row = wm * 32 + ((grp & 1) << 3) + r8;
        int a_kof = (grp >> 1) << 3;
        int b_n   = wn * 64 + ((grp >> 1) << 3) + r8;
        int b_kof = (grp & 1) << 3;
        int qr = lane >> 2, ql = lane & 3;
        int cbase = blockIdx.x * NT + wn * 64 + ql * 2;

        int al_ph[NBUF] = {0, 0, 0, 0};
        #pragma unroll 1
        for (int m = 0; m < 8; m++) {
            uint32_t hsum[2][8][2];                      // f16x2 running sums
            #pragma unroll
            for (int i = 0; i < 2; i++)
                #pragma unroll
                for (int j = 0; j < 8; j++)
                    hsum[i][j][0] = hsum[i][j][1] = 0u;

            #pragma unroll 1
            for (int kc = 0; kc < 8; kc++) {
                int g = m * 8 + kc, buf = g & (NBUF - 1);
                MBARRIER_WAIT_PARITY(MB_AL + 16 * buf, al_ph[buf]); al_ph[buf] ^= 1;
                uint32_t abuf = sb + A_OFF + buf * CHUNK_BYTES;

                uint32_t acch[2][8][2];
                #pragma unroll
                for (int i = 0; i < 2; i++)
                    #pragma unroll
                    for (int j = 0; j < 8; j++)
                        acch[i][j][0] = acch[i][j][1] = 0u;

                #pragma unroll
                for (int ks = 0; ks < 4; ks++) {
                    int k = ks * 16;
                    uint32_t a[2][4], b[4][4];
                    ldsm_x4(a[0], chunk_addr(abuf, a_row,      k + a_kof));
                    ldsm_x4(a[1], chunk_addr(abuf, a_row + 16, k + a_kof));
                    #pragma unroll
                    for (int jj = 0; jj < 4; jj++)
                        ldsm_x4(b[jj], sw_addr(sb + B_OFF, b_n + jj * 16, kc * 64 + k + b_kof));
                    if (ks == 3 && lane == 0) MBARRIER_ARRIVE(MB_AC + 16 * buf);
                    #pragma unroll
                    for (int i = 0; i < 2; i++)
                        #pragma unroll
                        for (int j = 0; j < 8; j++)
                            mma_h(acch[i][j], a[i],
                                  b[j >> 1][(j & 1) * 2], b[j >> 1][(j & 1) * 2 + 1]);
                }

                // accumulate chunk sum in f16x2 (32 HADD2)
                #pragma unroll
                for (int i = 0; i < 2; i++)
                    #pragma unroll
                    for (int j = 0; j < 8; j++) {
                        hsum[i][j][0] = hadd2(hsum[i][j][0], acch[i][j][0]);
                        hsum[i][j][1] = hadd2(hsum[i][j][1], acch[i][j][1]);
                    }
            }

            // fused epilogue: exp2(min(v*K, K) - K), label handled exactly by k_fix
            #pragma unroll
            for (int i = 0; i < 2; i++) {
                #pragma unroll
                for (int h = 0; h < 2; h++) {
                    int R = m * 128 + wm * 32 + i * 16 + h * 8 + qr;
                    int lbl = g_labels[R];
                    float sum = 0.0f;
                    #pragma unroll
                    for (int j = 0; j < 8; j++) {
                        float2 p = __half22float2(*reinterpret_cast<__half2*>(&hsum[i][j][h]));
                        #pragma unroll
                        for (int e = 0; e < 2; e++) {
                            int c = cbase + j * 8 + e;
                            float v = (e == 0) ? p.x : p.y;
                            float x = ex2f(fminf(v * K_LOG2E, K_LOG2E) - K_LOG2E);
                            if (c != lbl) sum += x;
                        }
                    }
                    sum += __shfl_xor_sync(0xFFFFFFFFu, sum, 1);
                    sum += __shfl_xor_sync(0xFFFFFFFFu, sum, 2);
                    if (ql == 0) atomicAdd(&g_rowsum[R], sum);
                }
            }
        }
    }

    __syncthreads();
    if (tid == 0) {
        for (int i = 0; i < NBUF; i++) { MBAR_INVAL(MB_AL + 16 * i); MBAR_INVAL(MB_AC + 16 * i); }
    }
}

// ===================== final reduction =====================
__global__ void k_final(float* __restrict__ out) {
    __shared__ float sd[BATCH];
    int t = threadIdx.x;
    sd[t] = 64.0f + logf(g_rowsum[t]) - g_target[t];
    __syncthreads();
    for (int s = 512; s > 0; s >>= 1) {
        if (t < s) sd[t] += sd[t + s];
        __syncthreads();
    }
    if (t == 0) out[0] = sd[0] * (1.0f / (float)BATCH);
}

// ===================== launch =====================
extern "C" void kernel_launch(void* const* d_in, const int* in_sizes, int n_in,
                              void* d_out, int out_size) {
    const float* emb = (const float*)d_in[0];
    const float* w   = (const float*)d_in[1];
    const int*   lw  = (const int*)d_in[2];
    float* out = (float*)d_out;

    cudaFuncSetAttribute(k_gemm, cudaFuncAttributeMaxDynamicSharedMemorySize, 197632);

    k_labels<<<1, 256>>>(lw);
    k_prep_a<<<BATCH / 8, 256>>>(emb);
    k_fix<<<BATCH / 8, 256>>>(emb, w);
    k_gemm<<<NTILES, 288, 197632>>>(w);
    k_final<<<1, BATCH>>>(out);
}

// round 12
// speedup vs baseline: 1.0881x; 1.0881x over previous
#include <cuda_runtime.h>
#include <cuda_fp16.h>
#include <cstdint>

// ===================== problem constants =====================
#define BATCH 1024
#define EMB 512
#define NCLS 200000
#define NT 128                   // classes per CTA tile
#define NTILES 1563              // ceil(NCLS / NT)
#define TILE_BYTES 131072        // 128 rows x 512 k x 2B (fp16 tile)
#define CHUNK_BYTES 16384        // 128 rows x 64 k fp16 (pipeline chunk)
#define NBUF 4
#define NCHUNKS 64               // 8 m-tiles x 8 chunks
#define SCALE_S 64.0f
#define COS_M 0.877582561890373f
#define SIN_M 0.479425538604203f
#define K_LOG2E 92.332482616893657f   // 64 * log2(e)

// ===================== device scratch =====================
__device__ __align__(1024) unsigned char g_A[8 * TILE_BYTES];  // 1 MB fp16 tiled embeddings
__device__ float g_rowsum[BATCH];
__device__ float g_target[BATCH];
__device__ int   g_labels[BATCH];

#define DEVINL __device__ __forceinline__

// ===================== PTX helpers =====================
DEVINL uint32_t smem_u32(const void* p) {
    uint32_t a;
    asm("{ .reg .u64 t; cvta.to.shared.u64 t, %1; cvt.u32.u64 %0, t; }" : "=r"(a) : "l"(p));
    return a;
}

#define MBARRIER_INIT(addr, cnt) \
    asm volatile("mbarrier.init.shared.b64 [%0], %1;" :: "r"((uint32_t)(addr)), "r"((uint32_t)(cnt)) : "memory")

#define MBARRIER_EXPECT_TX(addr, bytes) \
    asm volatile("mbarrier.arrive.expect_tx.shared.b64 _, [%0], %1;" :: "r"((uint32_t)(addr)), "r"((uint32_t)(bytes)) : "memory")

#define MBARRIER_ARRIVE(addr) \
    asm volatile("mbarrier.arrive.shared.b64 _, [%0];" :: "r"((uint32_t)(addr)) : "memory")

#define MBARRIER_WAIT_PARITY(addr, parity) do {                                   \
    asm volatile(                                                                 \
        "{\n\t.reg .pred P1;\n\t"                                                 \
        "WAIT_LOOP_%=:\n\t"                                                       \
        "mbarrier.try_wait.parity.acquire.cta.shared::cta.b64 P1, [%0], %1, 0x989680;\n\t" \
        "@P1 bra.uni WAIT_DONE_%=;\n\t"                                           \
        "bra.uni WAIT_LOOP_%=;\n\t"                                               \
        "WAIT_DONE_%=:\n\t}"                                                      \
        :: "r"((uint32_t)(addr)), "r"((uint32_t)(parity)) : "memory");            \
} while (0)

#define MBAR_INVAL(addr) \
    asm volatile("mbarrier.inval.shared.b64 [%0];" :: "r"((uint32_t)(addr)) : "memory")

#define BULK_G2S(dst_smem, src_gmem, bytes, mbar)                                                   \
    asm volatile("cp.async.bulk.shared::cluster.global.mbarrier::complete_tx::bytes [%0], [%1], %2, [%3];" \
        :: "r"((uint32_t)(dst_smem)), "l"(src_gmem), "r"((uint32_t)(bytes)), "r"((uint32_t)(mbar)) : "memory")

DEVINL void ldsm_x4(uint32_t* r, uint32_t addr) {
    asm volatile("ldmatrix.sync.aligned.m8n8.x4.shared.b16 {%0,%1,%2,%3}, [%4];"
                 : "=r"(r[0]), "=r"(r[1]), "=r"(r[2]), "=r"(r[3]) : "r"(addr));
}

// fp16 MMA with fp16 accumulate: D(2 regs) = A(4) * B(2) + C(2)
DEVINL void mma_h(uint32_t* c, const uint32_t* a, uint32_t b0, uint32_t b1) {
    asm volatile(
        "mma.sync.aligned.m16n8k16.row.col.f16.f16.f16.f16 "
        "{%0,%1}, {%2,%3,%4,%5}, {%6,%7}, {%0,%1};"
        : "+r"(c[0]), "+r"(c[1])
        : "r"(a[0]), "r"(a[1]), "r"(a[2]), "r"(a[3]), "r"(b0), "r"(b1));
}

DEVINL uint32_t hadd2(uint32_t x, uint32_t y) {
    uint32_t r;
    asm("add.f16x2 %0, %1, %2;" : "=r"(r) : "r"(x), "r"(y));
    return r;
}

DEVINL float ex2f(float x) {
    float r;
    asm("ex2.approx.f32 %0, %1;" : "=f"(r) : "f"(x));
    return r;
}

// fp16 element (row 0..127, k 0..511) inside a 128-row tiled region:
// [k/64 superblock: 16KB][row/8 group: 1KB][SW128 atom: 8 rows x 128B]
DEVINL uint32_t sw_addr(uint32_t base, int row, int k) {
    return base + (uint32_t)(((k >> 6) << 14) + ((row >> 3) << 10) + ((row & 7) << 7)
                             + (((k & 63) << 1) ^ ((row & 7) << 4)));
}

// fp16 element (row 0..127, k 0..63) inside one 16KB chunk buffer
DEVINL uint32_t chunk_addr(uint32_t base, int row, int k) {
    return base + (uint32_t)(((row >> 3) << 10) + ((row & 7) << 7)
                             + ((k << 1) ^ ((row & 7) << 4)));
}

// gmem scratch side (A): element (rr 0..127, k 0..511) in a 128x512 tile
DEVINL uint32_t tile_elem_off(int rr, int k) {
    return (uint32_t)(((k >> 6) << 14) + ((rr >> 3) << 10) + ((rr & 7) << 7)
                      + (((k & 63) << 1) ^ ((rr & 7) << 4)));
}

// ===================== prep =====================
DEVINL float dot4(float4 v) { return v.x * v.x + v.y * v.y + v.z * v.z + v.w * v.w; }
DEVINL uint32_t pk2h(float a, float b) {
    __half2 h = __floats2half2_rn(a, b);
    return *reinterpret_cast<uint32_t*>(&h);
}

__global__ void k_prep_a(const float* __restrict__ emb) {
    int r = blockIdx.x * 8 + (threadIdx.x >> 5);
    int lane = threadIdx.x & 31;
    unsigned char* base = g_A + (size_t)(r >> 7) * TILE_BYTES;
    int rr = r & 127;
    const float4* s = reinterpret_cast<const float4*>(emb + (size_t)r * EMB);
    float4 x0 = s[2 * lane], x1 = s[2 * lane + 1];
    float4 x2 = s[64 + 2 * lane], x3 = s[65 + 2 * lane];
    float ss = dot4(x0) + dot4(x1) + dot4(x2) + dot4(x3);
    #pragma unroll
    for (int o = 16; o; o >>= 1) ss += __shfl_xor_sync(0xFFFFFFFFu, ss, o);
    float inv = 1.0f / fmaxf(sqrtf(ss), 1e-12f);
    uint4 a, b;
    a.x = pk2h(x0.x * inv, x0.y * inv); a.y = pk2h(x0.z * inv, x0.w * inv);
    a.z = pk2h(x1.x * inv, x1.y * inv); a.w = pk2h(x1.z * inv, x1.w * inv);
    b.x = pk2h(x2.x * inv, x2.y * inv); b.y = pk2h(x2.z * inv, x2.w * inv);
    b.z = pk2h(x3.x * inv, x3.y * inv); b.w = pk2h(x3.z * inv, x3.w * inv);
    *reinterpret_cast<uint4*>(base + tile_elem_off(rr, 8 * lane)) = a;
    *reinterpret_cast<uint4*>(base + tile_elem_off(rr, 256 + 8 * lane)) = b;
}

// labels: detect int64 vs int32 (odd 32-bit words all zero => int64), zero rowsum
__global__ void k_labels(const int* __restrict__ lw) {
    __shared__ int s64;
    int tid = threadIdx.x;
    if (tid == 0) s64 = 1;
    __syncthreads();
    if (tid < 64) {
        if (lw[2 * tid + 1] != 0) atomicExch(&s64, 0);
    }
    __syncthreads();
    int is64 = s64;
    for (int i = tid; i < BATCH; i += 256) {
        g_labels[i] = is64 ? lw[2 * i] : lw[i];
        g_rowsum[i] = 0.0f;
    }
}

// exact fp32 target logit per row: margined, added to rowsum (GEMM skips label col)
__global__ void k_fix(const float* __restrict__ emb, const float* __restrict__ w) {
    int wrp = (blockIdx.x * blockDim.x + threadIdx.x) >> 5;   // 0..1023
    int lane = threadIdx.x & 31;
    int lbl = g_labels[wrp];
    const float4* e4 = reinterpret_cast<const float4*>(emb + (size_t)wrp * EMB);
    const float4* w4 = reinterpret_cast<const float4*>(w + (size_t)lbl * EMB);
    float ee = 0.f, ww = 0.f, ew = 0.f;
    #pragma unroll
    for (int i = 0; i < 4; i++) {
        float4 a = e4[lane + 32 * i], b = w4[lane + 32 * i];
        ee += dot4(a); ww += dot4(b);
        ew += a.x * b.x + a.y * b.y + a.z * b.z + a.w * b.w;
    }
    #pragma unroll
    for (int o = 16; o; o >>= 1) {
        ee += __shfl_xor_sync(0xFFFFFFFFu, ee, o);
        ww += __shfl_xor_sync(0xFFFFFFFFu, ww, o);
        ew += __shfl_xor_sync(0xFFFFFFFFu, ew, o);
    }
    if (lane == 0) {
        float t = ew / (fmaxf(sqrtf(ee), 1e-12f) * fmaxf(sqrtf(ww), 1e-12f));
        t = fminf(fmaxf(t, -1.0f), 1.0f);
        t = fminf(fmaxf(t, -1.0f + 1e-7f), 1.0f - 1e-7f);
        float lg = (t * COS_M - sqrtf(fmaxf(1.0f - t * t, 0.0f)) * SIN_M) * SCALE_S;
        g_target[wrp] = lg;
        atomicAdd(&g_rowsum[wrp], __expf(lg - 64.0f));
    }
}

// ===================== fp16 GEMM + fused W-normalize + softmax-partial epilogue ===
// 544 threads: warps 0-15 compute (4 m-slices x 4 n-slices, warp tile 32x32),
// warp 16 = loader. B tile (128 classes x 512 k fp16 = 128 KB) SMEM-resident,
// built by the prologue (W read from DRAM exactly once, f32 -> normalized fp16).
// fp16 accumulate; chunk sums via HADD2; f32 conversion once per m-tile.
__global__ __launch_bounds__(544, 1) void k_gemm(const float* __restrict__ wraw) {
    extern __shared__ unsigned char smem[];
    uint32_t sb = smem_u32(smem);
    int tid = threadIdx.x, wid = tid >> 5, lane = tid & 31;

    const uint32_t MB_AL = sb + 32;    // full barriers [4]
    const uint32_t MB_AC = sb + 128;   // consumed barriers [4]
    const uint32_t A_OFF = 1024;       // 4 x 16KB chunk buffers
    const uint32_t B_OFF = 66560;      // 1024-aligned; +128KB => 197632 total

    if (tid == 0) {
        for (int i = 0; i < NBUF; i++) {
            MBARRIER_INIT(MB_AL + 16 * i, 1);
            MBARRIER_INIT(MB_AC + 16 * i, 16);   // 16 compute warps
        }
    }
    __syncthreads();

    if (wid == 16) {
        if (lane == 0) {
            #pragma unroll
            for (int g = 0; g < NBUF; g++) {
                MBARRIER_EXPECT_TX(MB_AL + 16 * g, CHUNK_BYTES);
                BULK_G2S(sb + A_OFF + g * CHUNK_BYTES, g_A + (size_t)g * CHUNK_BYTES,
                         CHUNK_BYTES, MB_AL + 16 * g);
            }
            int ac_ph[NBUF] = {0, 0, 0, 0};
            for (int g = NBUF; g < NCHUNKS; g++) {
                int buf = g & (NBUF - 1);
                MBARRIER_WAIT_PARITY(MB_AC + 16 * buf, ac_ph[buf]); ac_ph[buf] ^= 1;
                MBARRIER_EXPECT_TX(MB_AL + 16 * buf, CHUNK_BYTES);
                BULK_G2S(sb + A_OFF + buf * CHUNK_BYTES, g_A + (size_t)g * CHUNK_BYTES,
                         CHUNK_BYTES, MB_AL + 16 * buf);
            }
        }
    } else {
        // ---- prologue: normalize this CTA's 128 W rows into SMEM B tile (fp16) ----
        // 16 warps x 8 rows, batched 2 rows/iter (low register footprint)
        #pragma unroll 1
        for (int rb = 0; rb < 4; rb++) {
            int r0 = wid * 8 + rb * 2;
            float4 x[2][4];
            #pragma unroll
            for (int rr = 0; rr < 2; rr++) {
                int c = blockIdx.x * NT + r0 + rr;
                if (c < NCLS) {
                    const float4* s = reinterpret_cast<const float4*>(wraw + (size_t)c * EMB);
                    #pragma unroll
                    for (int q = 0; q < 4; q++) x[rr][q] = s[q * 32 + lane];  // coalesced
                } else {
                    #pragma unroll
                    for (int q = 0; q < 4; q++) x[rr][q] = make_float4(0.f, 0.f, 0.f, 0.f);
                }
            }
            #pragma unroll
            for (int rr = 0; rr < 2; rr++) {
                float ss = dot4(x[rr][0]) + dot4(x[rr][1]) + dot4(x[rr][2]) + dot4(x[rr][3]);
                #pragma unroll
                for (int o = 16; o; o >>= 1) ss += __shfl_xor_sync(0xFFFFFFFFu, ss, o);
                float inv = 1.0f / fmaxf(sqrtf(ss), 1e-12f);
                #pragma unroll
                for (int q = 0; q < 4; q++) {
                    uint32_t lo = pk2h(x[rr][q].x * inv, x[rr][q].y * inv);
                    uint32_t hi = pk2h(x[rr][q].z * inv, x[rr][q].w * inv);
                    uint32_t addr = sw_addr(sb + B_OFF, r0 + rr, q * 128 + lane * 4);
                    asm volatile("st.shared.v2.b32 [%0], {%1, %2};" :: "r"(addr), "r"(lo), "r"(hi) : "memory");
                }
            }
        }
        asm volatile("bar.sync 1, 512;" ::: "memory");   // compute warps only

        // ---- main loop ----
        int wm = wid & 3, wn = wid >> 2;                 // 4 m-slices x 4 n-slices
        int grp = lane >> 3, r8 = lane & 7;
        int a_row = wm * 32 + ((grp & 1) << 3) + r8;
        int a_kof = (grp >> 1) << 3;
        int b_n   = wn * 32 + ((grp >> 1) << 3) + r8;
        int b_kof = (grp & 1) << 3;
        int qr = lane >> 2, ql = lane & 3;
        int cbase = blockIdx.x * NT + wn * 32 + ql * 2;

        int al_ph[NBUF] = {0, 0, 0, 0};
        #pragma unroll 1
        for (int m = 0; m < 8; m++) {
            uint32_t hsum[2][4][2];                      // f16x2 running sums
            #pragma unroll
            for (int i = 0; i < 2; i++)
                #pragma unroll
                for (int j = 0; j < 4; j++)
                    hsum[i][j][0] = hsum[i][j][1] = 0u;

            #pragma unroll 1
            for (int kc = 0; kc < 8; kc++) {
                int g = m * 8 + kc, buf = g & (NBUF - 1);
                MBARRIER_WAIT_PARITY(MB_AL + 16 * buf, al_ph[buf]); al_ph[buf] ^= 1;
                uint32_t abuf = sb + A_OFF + buf * CHUNK_BYTES;

                uint32_t acch[2][4][2];
                #pragma unroll
                for (int i = 0; i < 2; i++)
                    #pragma unroll
                    for (int j = 0; j < 4; j++)
                        acch[i][j][0] = acch[i][j][1] = 0u;

                #pragma unroll
                for (int ks = 0; ks < 4; ks++) {
                    int k = ks * 16;
                    uint32_t a[2][4], b[2][4];
                    ldsm_x4(a[0], chunk_addr(abuf, a_row,      k + a_kof));
                    ldsm_x4(a[1], chunk_addr(abuf, a_row + 16, k + a_kof));
                    ldsm_x4(b[0], sw_addr(sb + B_OFF, b_n,      kc * 64 + k + b_kof));
                    ldsm_x4(b[1], sw_addr(sb + B_OFF, b_n + 16, kc * 64 + k + b_kof));
                    if (ks == 3 && lane == 0) MBARRIER_ARRIVE(MB_AC + 16 * buf);
                    #pragma unroll
                    for (int i = 0; i < 2; i++)
                        #pragma unroll
                        for (int j = 0; j < 4; j++)
                            mma_h(acch[i][j], a[i],
                                  b[j >> 1][(j & 1) * 2], b[j >> 1][(j & 1) * 2 + 1]);
                }

                // accumulate chunk sum in f16x2 (16 HADD2)
                #pragma unroll
                for (int i = 0; i < 2; i++)
                    #pragma unroll
                    for (int j = 0; j < 4; j++) {
                        hsum[i][j][0] = hadd2(hsum[i][j][0], acch[i][j][0]);
                        hsum[i][j][1] = hadd2(hsum[i][j][1], acch[i][j][1]);
                    }
            }

            // fused epilogue: exp2(min(v*K, K) - K), label handled exactly by k_fix
            #pragma unroll
            for (int i = 0; i < 2; i++) {
                #pragma unroll
                for (int h = 0; h < 2; h++) {
                    int R = m * 128 + wm * 32 + i * 16 + h * 8 + qr;
                    int lbl = g_labels[R];
                    float sum = 0.0f;
                    #pragma unroll
                    for (int j = 0; j < 4; j++) {
                        float2 p = __half22float2(*reinterpret_cast<__half2*>(&hsum[i][j][h]));
                        #pragma unroll
                        for (int e = 0; e < 2; e++) {
                            int c = cbase + j * 8 + e;
                            float v = (e == 0) ? p.x : p.y;
                            float x = ex2f(fminf(v * K_LOG2E, K_LOG2E) - K_LOG2E);
                            if (c != lbl) sum += x;
                        }
                    }
                    sum += __shfl_xor_sync(0xFFFFFFFFu, sum, 1);
                    sum += __shfl_xor_sync(0xFFFFFFFFu, sum, 2);
                    if (ql == 0) atomicAdd(&g_rowsum[R], sum);
                }
            }
        }
    }

    __syncthreads();
    if (tid == 0) {
        for (int i = 0; i < NBUF; i++) { MBAR_INVAL(MB_AL + 16 * i); MBAR_INVAL(MB_AC + 16 * i); }
    }
}

// ===================== final reduction =====================
__global__ void k_final(float* __restrict__ out) {
    __shared__ float sd[BATCH];
    int t = threadIdx.x;
    sd[t] = 64.0f + logf(g_rowsum[t]) - g_target[t];
    __syncthreads();
    for (int s = 512; s > 0; s >>= 1) {
        if (t < s) sd[t] += sd[t + s];
        __syncthreads();
    }
    if (t == 0) out[0] = sd[0] * (1.0f / (float)BATCH);
}

// ===================== launch =====================
extern "C" void kernel_launch(void* const* d_in, const int* in_sizes, int n_in,
                              void* d_out, int out_size) {
    const float* emb = (const float*)d_in[0];
    const float* w   = (const float*)d_in[1];
    const int*   lw  = (const int*)d_in[2];
    float* out = (float*)d_out;

    cudaFuncSetAttribute(k_gemm, cudaFuncAttributeMaxDynamicSharedMemorySize, 197632);

    k_labels<<<1, 256>>>(lw);
    k_prep_a<<<BATCH / 8, 256>>>(emb);
    k_fix<<<BATCH / 8, 256>>>(emb, w);
    k_gemm<<<NTILES, 544, 197632>>>(w);
    k_final<<<1, BATCH>>>(out);
}

// round 13
// speedup vs baseline: 1.1210x; 1.0302x over previous
#include <cuda_runtime.h>
#include <cuda_fp16.h>
#include <cstdint>

// ===================== problem constants =====================
#define BATCH 1024
#define EMB 512
#define NCLS 200000
#define NT 128                   // classes per CTA tile
#define NTILES 1563              // ceil(NCLS / NT)
#define TILE_BYTES 131072        // 128 rows x 512 k x 2B (fp16 tile)
#define CHUNK_BYTES 16384        // 128 rows x 64 k fp16 (pipeline chunk)
#define NBUF 4
#define NCHUNKS 64               // 8 m-tiles x 8 chunks
#define SCALE_S 64.0f
#define COS_M 0.877582561890373f
#define SIN_M 0.479425538604203f
#define K_LOG2E 92.332482616893657f   // 64 * log2(e)

// ===================== device scratch =====================
__device__ __align__(1024) unsigned char g_A[8 * TILE_BYTES];  // 1 MB fp16 tiled embeddings
__device__ float g_rowsum[BATCH];
__device__ float g_target[BATCH];
__device__ int   g_labels[BATCH];

#define DEVINL __device__ __forceinline__

// ===================== PTX helpers =====================
DEVINL uint32_t smem_u32(const void* p) {
    uint32_t a;
    asm("{ .reg .u64 t; cvta.to.shared.u64 t, %1; cvt.u32.u64 %0, t; }" : "=r"(a) : "l"(p));
    return a;
}

#define MBARRIER_INIT(addr, cnt) \
    asm volatile("mbarrier.init.shared.b64 [%0], %1;" :: "r"((uint32_t)(addr)), "r"((uint32_t)(cnt)) : "memory")

#define MBARRIER_EXPECT_TX(addr, bytes) \
    asm volatile("mbarrier.arrive.expect_tx.shared.b64 _, [%0], %1;" :: "r"((uint32_t)(addr)), "r"((uint32_t)(bytes)) : "memory")

#define MBARRIER_ARRIVE(addr) \
    asm volatile("mbarrier.arrive.shared.b64 _, [%0];" :: "r"((uint32_t)(addr)) : "memory")

#define MBARRIER_WAIT_PARITY(addr, parity) do {                                   \
    asm volatile(                                                                 \
        "{\n\t.reg .pred P1;\n\t"                                                 \
        "WAIT_LOOP_%=:\n\t"                                                       \
        "mbarrier.try_wait.parity.acquire.cta.shared::cta.b64 P1, [%0], %1, 0x989680;\n\t" \
        "@P1 bra.uni WAIT_DONE_%=;\n\t"                                           \
        "bra.uni WAIT_LOOP_%=;\n\t"                                               \
        "WAIT_DONE_%=:\n\t}"                                                      \
        :: "r"((uint32_t)(addr)), "r"((uint32_t)(parity)) : "memory");            \
} while (0)

#define MBAR_INVAL(addr) \
    asm volatile("mbarrier.inval.shared.b64 [%0];" :: "r"((uint32_t)(addr)) : "memory")

#define BULK_G2S(dst_smem, src_gmem, bytes, mbar)                                                   \
    asm volatile("cp.async.bulk.shared::cluster.global.mbarrier::complete_tx::bytes [%0], [%1], %2, [%3];" \
        :: "r"((uint32_t)(dst_smem)), "l"(src_gmem), "r"((uint32_t)(bytes)), "r"((uint32_t)(mbar)) : "memory")

DEVINL void ldsm_x4(uint32_t* r, uint32_t addr) {
    asm volatile("ldmatrix.sync.aligned.m8n8.x4.shared.b16 {%0,%1,%2,%3}, [%4];"
                 : "=r"(r[0]), "=r"(r[1]), "=r"(r[2]), "=r"(r[3]) : "r"(addr));
}

// fp16 MMA with fp16 accumulate: D(2 regs) = A(4) * B(2) + C(2)
DEVINL void mma_h(uint32_t* c, const uint32_t* a, uint32_t b0, uint32_t b1) {
    asm volatile(
        "mma.sync.aligned.m16n8k16.row.col.f16.f16.f16.f16 "
        "{%0,%1}, {%2,%3,%4,%5}, {%6,%7}, {%0,%1};"
        : "+r"(c[0]), "+r"(c[1])
        : "r"(a[0]), "r"(a[1]), "r"(a[2]), "r"(a[3]), "r"(b0), "r"(b1));
}

DEVINL float ex2f(float x) {
    float r;
    asm("ex2.approx.f32 %0, %1;" : "=f"(r) : "f"(x));
    return r;
}

// fp16 element (row 0..127, k 0..511) inside a 128-row tiled region:
// [k/64 superblock: 16KB][row/8 group: 1KB][SW128 atom: 8 rows x 128B]
DEVINL uint32_t sw_addr(uint32_t base, int row, int k) {
    return base + (uint32_t)(((k >> 6) << 14) + ((row >> 3) << 10) + ((row & 7) << 7)
                             + (((k & 63) << 1) ^ ((row & 7) << 4)));
}

// fp16 element (row 0..127, k 0..63) inside one 16KB chunk buffer
DEVINL uint32_t chunk_addr(uint32_t base, int row, int k) {
    return base + (uint32_t)(((row >> 3) << 10) + ((row & 7) << 7)
                             + ((k << 1) ^ ((row & 7) << 4)));
}

// gmem scratch side (A): element (rr 0..127, k 0..511) in a 128x512 tile
DEVINL uint32_t tile_elem_off(int rr, int k) {
    return (uint32_t)(((k >> 6) << 14) + ((rr >> 3) << 10) + ((rr & 7) << 7)
                      + (((k & 63) << 1) ^ ((rr & 7) << 4)));
}

// ===================== prep =====================
DEVINL float dot4(float4 v) { return v.x * v.x + v.y * v.y + v.z * v.z + v.w * v.w; }
DEVINL uint32_t pk2h(float a, float b) {
    __half2 h = __floats2half2_rn(a, b);
    return *reinterpret_cast<uint32_t*>(&h);
}

__global__ void k_prep_a(const float* __restrict__ emb) {
    int r = blockIdx.x * 8 + (threadIdx.x >> 5);
    int lane = threadIdx.x & 31;
    unsigned char* base = g_A + (size_t)(r >> 7) * TILE_BYTES;
    int rr = r & 127;
    const float4* s = reinterpret_cast<const float4*>(emb + (size_t)r * EMB);
    float4 x0 = s[2 * lane], x1 = s[2 * lane + 1];
    float4 x2 = s[64 + 2 * lane], x3 = s[65 + 2 * lane];
    float ss = dot4(x0) + dot4(x1) + dot4(x2) + dot4(x3);
    #pragma unroll
    for (int o = 16; o; o >>= 1) ss += __shfl_xor_sync(0xFFFFFFFFu, ss, o);
    float inv = 1.0f / fmaxf(sqrtf(ss), 1e-12f);
    uint4 a, b;
    a.x = pk2h(x0.x * inv, x0.y * inv); a.y = pk2h(x0.z * inv, x0.w * inv);
    a.z = pk2h(x1.x * inv, x1.y * inv); a.w = pk2h(x1.z * inv, x1.w * inv);
    b.x = pk2h(x2.x * inv, x2.y * inv); b.y = pk2h(x2.z * inv, x2.w * inv);
    b.z = pk2h(x3.x * inv, x3.y * inv); b.w = pk2h(x3.z * inv, x3.w * inv);
    *reinterpret_cast<uint4*>(base + tile_elem_off(rr, 8 * lane)) = a;
    *reinterpret_cast<uint4*>(base + tile_elem_off(rr, 256 + 8 * lane)) = b;
}

// labels: detect int64 vs int32 (odd 32-bit words all zero => int64), zero rowsum
__global__ void k_labels(const int* __restrict__ lw) {
    __shared__ int s64;
    int tid = threadIdx.x;
    if (tid == 0) s64 = 1;
    __syncthreads();
    if (tid < 64) {
        if (lw[2 * tid + 1] != 0) atomicExch(&s64, 0);
    }
    __syncthreads();
    int is64 = s64;
    for (int i = tid; i < BATCH; i += 256) {
        g_labels[i] = is64 ? lw[2 * i] : lw[i];
        g_rowsum[i] = 0.0f;
    }
}

// exact fp32 target logit per row: margined, added to rowsum (GEMM skips label col)
__global__ void k_fix(const float* __restrict__ emb, const float* __restrict__ w) {
    int wrp = (blockIdx.x * blockDim.x + threadIdx.x) >> 5;   // 0..1023
    int lane = threadIdx.x & 31;
    int lbl = g_labels[wrp];
    const float4* e4 = reinterpret_cast<const float4*>(emb + (size_t)wrp * EMB);
    const float4* w4 = reinterpret_cast<const float4*>(w + (size_t)lbl * EMB);
    float ee = 0.f, ww = 0.f, ew = 0.f;
    #pragma unroll
    for (int i = 0; i < 4; i++) {
        float4 a = e4[lane + 32 * i], b = w4[lane + 32 * i];
        ee += dot4(a); ww += dot4(b);
        ew += a.x * b.x + a.y * b.y + a.z * b.z + a.w * b.w;
    }
    #pragma unroll
    for (int o = 16; o; o >>= 1) {
        ee += __shfl_xor_sync(0xFFFFFFFFu, ee, o);
        ww += __shfl_xor_sync(0xFFFFFFFFu, ww, o);
        ew += __shfl_xor_sync(0xFFFFFFFFu, ew, o);
    }
    if (lane == 0) {
        float t = ew / (fmaxf(sqrtf(ee), 1e-12f) * fmaxf(sqrtf(ww), 1e-12f));
        t = fminf(fmaxf(t, -1.0f), 1.0f);
        t = fminf(fmaxf(t, -1.0f + 1e-7f), 1.0f - 1e-7f);
        float lg = (t * COS_M - sqrtf(fmaxf(1.0f - t * t, 0.0f)) * SIN_M) * SCALE_S;
        g_target[wrp] = lg;
        atomicAdd(&g_rowsum[wrp], __expf(lg - 64.0f));
    }
}

// ===================== fp16 GEMM + fused W-normalize + softmax-partial epilogue ===
// 544 threads: warps 0-15 compute (4 m-slices x 4 n-slices, warp tile 32x32),
// warp 16 = loader. B tile (128 classes x 512 k fp16 = 128 KB) SMEM-resident,
// built by the prologue (W read from DRAM exactly once, f32 -> normalized fp16).
// fp16 MMA accumulators carry the full K=512 reduction (no flush ops at all).
__global__ __launch_bounds__(544, 1) void k_gemm(const float* __restrict__ wraw) {
    extern __shared__ unsigned char smem[];
    uint32_t sb = smem_u32(smem);
    int tid = threadIdx.x, wid = tid >> 5, lane = tid & 31;

    const uint32_t MB_AL = sb + 32;    // full barriers [4]
    const uint32_t MB_AC = sb + 128;   // consumed barriers [4]
    const uint32_t A_OFF = 1024;       // 4 x 16KB chunk buffers
    const uint32_t B_OFF = 66560;      // 1024-aligned; +128KB => 197632 total

    if (tid == 0) {
        for (int i = 0; i < NBUF; i++) {
            MBARRIER_INIT(MB_AL + 16 * i, 1);
            MBARRIER_INIT(MB_AC + 16 * i, 16);   // 16 compute warps
        }
    }
    __syncthreads();

    if (wid == 16) {
        if (lane == 0) {
            #pragma unroll
            for (int g = 0; g < NBUF; g++) {
                MBARRIER_EXPECT_TX(MB_AL + 16 * g, CHUNK_BYTES);
                BULK_G2S(sb + A_OFF + g * CHUNK_BYTES, g_A + (size_t)g * CHUNK_BYTES,
                         CHUNK_BYTES, MB_AL + 16 * g);
            }
            int ac_ph[NBUF] = {0, 0, 0, 0};
            for (int g = NBUF; g < NCHUNKS; g++) {
                int buf = g & (NBUF - 1);
                MBARRIER_WAIT_PARITY(MB_AC + 16 * buf, ac_ph[buf]); ac_ph[buf] ^= 1;
                MBARRIER_EXPECT_TX(MB_AL + 16 * buf, CHUNK_BYTES);
                BULK_G2S(sb + A_OFF + buf * CHUNK_BYTES, g_A + (size_t)g * CHUNK_BYTES,
                         CHUNK_BYTES, MB_AL + 16 * buf);
            }
        }
    } else {
        // ---- prologue: normalize this CTA's 128 W rows into SMEM B tile (fp16) ----
        // 16 warps x 8 rows, batched 2 rows/iter (low register footprint)
        #pragma unroll 1
        for (int rb = 0; rb < 4; rb++) {
            int r0 = wid * 8 + rb * 2;
            float4 x[2][4];
            #pragma unroll
            for (int rr = 0; rr < 2; rr++) {
                int c = blockIdx.x * NT + r0 + rr;
                if (c < NCLS) {
                    const float4* s = reinterpret_cast<const float4*>(wraw + (size_t)c * EMB);
                    #pragma unroll
                    for (int q = 0; q < 4; q++) x[rr][q] = s[q * 32 + lane];  // coalesced
                } else {
                    #pragma unroll
                    for (int q = 0; q < 4; q++) x[rr][q] = make_float4(0.f, 0.f, 0.f, 0.f);
                }
            }
            #pragma unroll
            for (int rr = 0; rr < 2; rr++) {
                float ss = dot4(x[rr][0]) + dot4(x[rr][1]) + dot4(x[rr][2]) + dot4(x[rr][3]);
                #pragma unroll
                for (int o = 16; o; o >>= 1) ss += __shfl_xor_sync(0xFFFFFFFFu, ss, o);
                float inv = 1.0f / fmaxf(sqrtf(ss), 1e-12f);
                #pragma unroll
                for (int q = 0; q < 4; q++) {
                    uint32_t lo = pk2h(x[rr][q].x * inv, x[rr][q].y * inv);
                    uint32_t hi = pk2h(x[rr][q].z * inv, x[rr][q].w * inv);
                    uint32_t addr = sw_addr(sb + B_OFF, r0 + rr, q * 128 + lane * 4);
                    asm volatile("st.shared.v2.b32 [%0], {%1, %2};" :: "r"(addr), "r"(lo), "r"(hi) : "memory");
                }
            }
        }
        asm volatile("bar.sync 1, 512;" ::: "memory");   // compute warps only

        // ---- main loop ----
        int wm = wid & 3, wn = wid >> 2;                 // 4 m-slices x 4 n-slices
        int grp = lane >> 3, r8 = lane & 7;
        int a_row = wm * 32 + ((grp & 1) << 3) + r8;
        int a_kof = (grp >> 1) << 3;
        int b_n   = wn * 32 + ((grp >> 1) << 3) + r8;
        int b_kof = (grp & 1) << 3;
        int qr = lane >> 2, ql = lane & 3;
        int cbase = blockIdx.x * NT + wn * 32 + ql * 2;

        int al_ph[NBUF] = {0, 0, 0, 0};
        #pragma unroll 1
        for (int m = 0; m < 8; m++) {
            uint32_t acch[2][4][2];                      // fp16x2 accumulators, full K
            #pragma unroll
            for (int i = 0; i < 2; i++)
                #pragma unroll
                for (int j = 0; j < 4; j++)
                    acch[i][j][0] = acch[i][j][1] = 0u;

            #pragma unroll 1
            for (int kc = 0; kc < 8; kc++) {
                int g = m * 8 + kc, buf = g & (NBUF - 1);
                MBARRIER_WAIT_PARITY(MB_AL + 16 * buf, al_ph[buf]); al_ph[buf] ^= 1;
                uint32_t abuf = sb + A_OFF + buf * CHUNK_BYTES;

                #pragma unroll
                for (int ks = 0; ks < 4; ks++) {
                    int k = ks * 16;
                    uint32_t a[2][4], b[2][4];
                    ldsm_x4(a[0], chunk_addr(abuf, a_row,      k + a_kof));
                    ldsm_x4(a[1], chunk_addr(abuf, a_row + 16, k + a_kof));
                    ldsm_x4(b[0], sw_addr(sb + B_OFF, b_n,      kc * 64 + k + b_kof));
                    ldsm_x4(b[1], sw_addr(sb + B_OFF, b_n + 16, kc * 64 + k + b_kof));
                    if (ks == 3 && lane == 0) MBARRIER_ARRIVE(MB_AC + 16 * buf);
                    #pragma unroll
                    for (int i = 0; i < 2; i++)
                        #pragma unroll
                        for (int j = 0; j < 4; j++)
                            mma_h(acch[i][j], a[i],
                                  b[j >> 1][(j & 1) * 2], b[j >> 1][(j & 1) * 2 + 1]);
                }
            }

            // fused epilogue: exp2(min(v*K, K) - K), label handled exactly by k_fix
            #pragma unroll
            for (int i = 0; i < 2; i++) {
                #pragma unroll
                for (int h = 0; h < 2; h++) {
                    int R = m * 128 + wm * 32 + i * 16 + h * 8 + qr;
                    int lbl = g_labels[R];
                    float sum = 0.0f;
                    #pragma unroll
                    for (int j = 0; j < 4; j++) {
                        float2 p = __half22float2(*reinterpret_cast<__half2*>(&acch[i][j][h]));
                        #pragma unroll
                        for (int e = 0; e < 2; e++) {
                            int c = cbase + j * 8 + e;
                            float v = (e == 0) ? p.x : p.y;
                            float x = ex2f(fminf(v * K_LOG2E, K_LOG2E) - K_LOG2E);
                            if (c != lbl) sum += x;
                        }
                    }
                    sum += __shfl_xor_sync(0xFFFFFFFFu, sum, 1);
                    sum += __shfl_xor_sync(0xFFFFFFFFu, sum, 2);
                    if (ql == 0) atomicAdd(&g_rowsum[R], sum);
                }
            }
        }
    }

    __syncthreads();
    if (tid == 0) {
        for (int i = 0; i < NBUF; i++) { MBAR_INVAL(MB_AL + 16 * i); MBAR_INVAL(MB_AC + 16 * i); }
    }
}

// ===================== final reduction =====================
__global__ void k_final(float* __restrict__ out) {
    __shared__ float sd[BATCH];
    int t = threadIdx.x;
    sd[t] = 64.0f + logf(g_rowsum[t]) - g_target[t];
    __syncthreads();
    for (int s = 512; s > 0; s >>= 1) {
        if (t < s) sd[t] += sd[t + s];
        __syncthreads();
    }
    if (t == 0) out[0] = sd[0] * (1.0f / (float)BATCH);
}

// ===================== launch =====================
extern "C" void kernel_launch(void* const* d_in, const int* in_sizes, int n_in,
                              void* d_out, int out_size) {
    const float* emb = (const float*)d_in[0];
    const float* w   = (const float*)d_in[1];
    const int*   lw  = (const int*)d_in[2];
    float* out = (float*)d_out;

    cudaFuncSetAttribute(k_gemm, cudaFuncAttributeMaxDynamicSharedMemorySize, 197632);

    k_labels<<<1, 256>>>(lw);
    k_prep_a<<<BATCH / 8, 256>>>(emb);
    k_fix<<<BATCH / 8, 256>>>(emb, w);
    k_gemm<<<NTILES, 544, 197632>>>(w);
    k_final<<<1, BATCH>>>(out);
}

// round 14
// speedup vs baseline: 1.1996x; 1.0701x over previous
#include <cuda_runtime.h>
#include <cuda_fp16.h>
#include <cstdint>

// ===================== problem constants =====================
#define BATCH 1024
#define EMB 512
#define NCLS 200000
#define NT 128                   // classes per CTA tile
#define NTILES 1563              // ceil(NCLS / NT)
#define TILE_BYTES 131072        // 128 rows x 512 k x 2B (fp16 tile in gmem scratch)
#define CHUNK_BYTES 32768        // 256 rows x 64 k fp16 (pipeline chunk, 2x16KB pieces)
#define NBUF 2
#define NCHUNKS 32               // 4 m-tiles x 8 chunks
#define SCALE_S 64.0f
#define COS_M 0.877582561890373f
#define SIN_M 0.479425538604203f
#define K_LOG2E 92.332482616893657f   // 64 * log2(e)

// ===================== device scratch =====================
__device__ __align__(1024) unsigned char g_A[8 * TILE_BYTES];  // 1 MB fp16 tiled embeddings
__device__ float g_rowsum[BATCH];
__device__ float g_target[BATCH];
__device__ int   g_labels[BATCH];

#define DEVINL __device__ __forceinline__

// ===================== PTX helpers =====================
DEVINL uint32_t smem_u32(const void* p) {
    uint32_t a;
    asm("{ .reg .u64 t; cvta.to.shared.u64 t, %1; cvt.u32.u64 %0, t; }" : "=r"(a) : "l"(p));
    return a;
}

#define MBARRIER_INIT(addr, cnt) \
    asm volatile("mbarrier.init.shared.b64 [%0], %1;" :: "r"((uint32_t)(addr)), "r"((uint32_t)(cnt)) : "memory")

#define MBARRIER_EXPECT_TX(addr, bytes) \
    asm volatile("mbarrier.arrive.expect_tx.shared.b64 _, [%0], %1;" :: "r"((uint32_t)(addr)), "r"((uint32_t)(bytes)) : "memory")

#define MBARRIER_ARRIVE(addr) \
    asm volatile("mbarrier.arrive.shared.b64 _, [%0];" :: "r"((uint32_t)(addr)) : "memory")

#define MBARRIER_WAIT_PARITY(addr, parity) do {                                   \
    asm volatile(                                                                 \
        "{\n\t.reg .pred P1;\n\t"                                                 \
        "WAIT_LOOP_%=:\n\t"                                                       \
        "mbarrier.try_wait.parity.acquire.cta.shared::cta.b64 P1, [%0], %1, 0x989680;\n\t" \
        "@P1 bra.uni WAIT_DONE_%=;\n\t"                                           \
        "bra.uni WAIT_LOOP_%=;\n\t"                                               \
        "WAIT_DONE_%=:\n\t}"                                                      \
        :: "r"((uint32_t)(addr)), "r"((uint32_t)(parity)) : "memory");            \
} while (0)

#define MBAR_INVAL(addr) \
    asm volatile("mbarrier.inval.shared.b64 [%0];" :: "r"((uint32_t)(addr)) : "memory")

#define BULK_G2S(dst_smem, src_gmem, bytes, mbar)                                                   \
    asm volatile("cp.async.bulk.shared::cluster.global.mbarrier::complete_tx::bytes [%0], [%1], %2, [%3];" \
        :: "r"((uint32_t)(dst_smem)), "l"(src_gmem), "r"((uint32_t)(bytes)), "r"((uint32_t)(mbar)) : "memory")

DEVINL void ldsm_x4(uint32_t* r, uint32_t addr) {
    asm volatile("ldmatrix.sync.aligned.m8n8.x4.shared.b16 {%0,%1,%2,%3}, [%4];"
                 : "=r"(r[0]), "=r"(r[1]), "=r"(r[2]), "=r"(r[3]) : "r"(addr));
}

// fp16 MMA with fp16 accumulate: D(2 regs) = A(4) * B(2) + C(2)
DEVINL void mma_h(uint32_t* c, const uint32_t* a, uint32_t b0, uint32_t b1) {
    asm volatile(
        "mma.sync.aligned.m16n8k16.row.col.f16.f16.f16.f16 "
        "{%0,%1}, {%2,%3,%4,%5}, {%6,%7}, {%0,%1};"
        : "+r"(c[0]), "+r"(c[1])
        : "r"(a[0]), "r"(a[1]), "r"(a[2]), "r"(a[3]), "r"(b0), "r"(b1));
}

DEVINL float ex2f(float x) {
    float r;
    asm("ex2.approx.f32 %0, %1;" : "=f"(r) : "f"(x));
    return r;
}

// fp16 element (row 0..127, k 0..511) inside a 128-row tiled region:
// [k/64 superblock: 16KB][row/8 group: 1KB][SW128 atom: 8 rows x 128B]
DEVINL uint32_t sw_addr(uint32_t base, int row, int k) {
    return base + (uint32_t)(((k >> 6) << 14) + ((row >> 3) << 10) + ((row & 7) << 7)
                             + (((k & 63) << 1) ^ ((row & 7) << 4)));
}

// fp16 element (row 0..255, k 0..63) inside one 32KB chunk buffer:
// [row/128 half: 16KB][(row&127)/8 group: 1KB][SW128 atom]
DEVINL uint32_t chunk_addr(uint32_t base, int row, int k) {
    return base + (uint32_t)(((row >> 7) << 14) + (((row & 127) >> 3) << 10) + ((row & 7) << 7)
                             + ((k << 1) ^ ((row & 7) << 4)));
}

// gmem scratch side (A): element (rr 0..127, k 0..511) in a 128x512 tile
DEVINL uint32_t tile_elem_off(int rr, int k) {
    return (uint32_t)(((k >> 6) << 14) + ((rr >> 3) << 10) + ((rr & 7) << 7)
                      + (((k & 63) << 1) ^ ((rr & 7) << 4)));
}

// ===================== prep =====================
DEVINL float dot4(float4 v) { return v.x * v.x + v.y * v.y + v.z * v.z + v.w * v.w; }
DEVINL uint32_t pk2h(float a, float b) {
    __half2 h = __floats2half2_rn(a, b);
    return *reinterpret_cast<uint32_t*>(&h);
}

__global__ void k_prep_a(const float* __restrict__ emb) {
    int r = blockIdx.x * 8 + (threadIdx.x >> 5);
    int lane = threadIdx.x & 31;
    unsigned char* base = g_A + (size_t)(r >> 7) * TILE_BYTES;
    int rr = r & 127;
    const float4* s = reinterpret_cast<const float4*>(emb + (size_t)r * EMB);
    float4 x0 = s[2 * lane], x1 = s[2 * lane + 1];
    float4 x2 = s[64 + 2 * lane], x3 = s[65 + 2 * lane];
    float ss = dot4(x0) + dot4(x1) + dot4(x2) + dot4(x3);
    #pragma unroll
    for (int o = 16; o; o >>= 1) ss += __shfl_xor_sync(0xFFFFFFFFu, ss, o);
    float inv = 1.0f / fmaxf(sqrtf(ss), 1e-12f);
    uint4 a, b;
    a.x = pk2h(x0.x * inv, x0.y * inv); a.y = pk2h(x0.z * inv, x0.w * inv);
    a.z = pk2h(x1.x * inv, x1.y * inv); a.w = pk2h(x1.z * inv, x1.w * inv);
    b.x = pk2h(x2.x * inv, x2.y * inv); b.y = pk2h(x2.z * inv, x2.w * inv);
    b.z = pk2h(x3.x * inv, x3.y * inv); b.w = pk2h(x3.z * inv, x3.w * inv);
    *reinterpret_cast<uint4*>(base + tile_elem_off(rr, 8 * lane)) = a;
    *reinterpret_cast<uint4*>(base + tile_elem_off(rr, 256 + 8 * lane)) = b;
}

// labels: detect int64 vs int32 (odd 32-bit words all zero => int64), zero rowsum
__global__ void k_labels(const int* __restrict__ lw) {
    __shared__ int s64;
    int tid = threadIdx.x;
    if (tid == 0) s64 = 1;
    __syncthreads();
    if (tid < 64) {
        if (lw[2 * tid + 1] != 0) atomicExch(&s64, 0);
    }
    __syncthreads();
    int is64 = s64;
    for (int i = tid; i < BATCH; i += 256) {
        g_labels[i] = is64 ? lw[2 * i] : lw[i];
        g_rowsum[i] = 0.0f;
    }
}

// exact fp32 target logit per row: margined, added to rowsum (GEMM skips label col)
__global__ void k_fix(const float* __restrict__ emb, const float* __restrict__ w) {
    int wrp = (blockIdx.x * blockDim.x + threadIdx.x) >> 5;   // 0..1023
    int lane = threadIdx.x & 31;
    int lbl = g_labels[wrp];
    const float4* e4 = reinterpret_cast<const float4*>(emb + (size_t)wrp * EMB);
    const float4* w4 = reinterpret_cast<const float4*>(w + (size_t)lbl * EMB);
    float ee = 0.f, ww = 0.f, ew = 0.f;
    #pragma unroll
    for (int i = 0; i < 4; i++) {
        float4 a = e4[lane + 32 * i], b = w4[lane + 32 * i];
        ee += dot4(a); ww += dot4(b);
        ew += a.x * b.x + a.y * b.y + a.z * b.z + a.w * b.w;
    }
    #pragma unroll
    for (int o = 16; o; o >>= 1) {
        ee += __shfl_xor_sync(0xFFFFFFFFu, ee, o);
        ww += __shfl_xor_sync(0xFFFFFFFFu, ww, o);
        ew += __shfl_xor_sync(0xFFFFFFFFu, ew, o);
    }
    if (lane == 0) {
        float t = ew / (fmaxf(sqrtf(ee), 1e-12f) * fmaxf(sqrtf(ww), 1e-12f));
        t = fminf(fmaxf(t, -1.0f), 1.0f);
        t = fminf(fmaxf(t, -1.0f + 1e-7f), 1.0f - 1e-7f);
        float lg = (t * COS_M - sqrtf(fmaxf(1.0f - t * t, 0.0f)) * SIN_M) * SCALE_S;
        g_target[wrp] = lg;
        atomicAdd(&g_rowsum[wrp], __expf(lg - 64.0f));
    }
}

// ===================== fp16 GEMM + fused W-normalize + softmax-partial epilogue ===
// 544 threads: warps 0-15 compute (8 m-slices x 2 n-slices, warp tile 32x64 over
// 256-row m-tiles), warp 16 = loader. B tile (128 classes x 512 k fp16 = 128 KB)
// SMEM-resident, built by the prologue. fp16 MMA accumulators carry full K=512.
__global__ __launch_bounds__(544, 1) void k_gemm(const float* __restrict__ wraw) {
    extern __shared__ unsigned char smem[];
    uint32_t sb = smem_u32(smem);
    int tid = threadIdx.x, wid = tid >> 5, lane = tid & 31;

    const uint32_t MB_AL = sb + 32;    // full barriers [2]
    const uint32_t MB_AC = sb + 96;    // consumed barriers [2]
    const uint32_t A_OFF = 1024;       // 2 x 32KB chunk buffers
    const uint32_t B_OFF = 66560;      // 1024-aligned; +128KB => 197632 total

    if (tid == 0) {
        for (int i = 0; i < NBUF; i++) {
            MBARRIER_INIT(MB_AL + 16 * i, 1);
            MBARRIER_INIT(MB_AC + 16 * i, 16);   // 16 compute warps
        }
    }
    __syncthreads();

    if (wid == 16) {
        if (lane == 0) {
            // chunk g: m = g>>3 (256-row m-tile), kc = g&7 (64-k superblock)
            #pragma unroll
            for (int g = 0; g < NBUF; g++) {
                const unsigned char* src = g_A + (size_t)(2 * (g >> 3)) * TILE_BYTES + (g & 7) * 16384;
                MBARRIER_EXPECT_TX(MB_AL + 16 * g, CHUNK_BYTES);
                BULK_G2S(sb + A_OFF + g * CHUNK_BYTES, src, 16384, MB_AL + 16 * g);
                BULK_G2S(sb + A_OFF + g * CHUNK_BYTES + 16384, src + TILE_BYTES, 16384, MB_AL + 16 * g);
            }
            int ac_ph[NBUF] = {0, 0};
            for (int g = NBUF; g < NCHUNKS; g++) {
                int buf = g & (NBUF - 1);
                MBARRIER_WAIT_PARITY(MB_AC + 16 * buf, ac_ph[buf]); ac_ph[buf] ^= 1;
                const unsigned char* src = g_A + (size_t)(2 * (g >> 3)) * TILE_BYTES + (g & 7) * 16384;
                MBARRIER_EXPECT_TX(MB_AL + 16 * buf, CHUNK_BYTES);
                BULK_G2S(sb + A_OFF + buf * CHUNK_BYTES, src, 16384, MB_AL + 16 * buf);
                BULK_G2S(sb + A_OFF + buf * CHUNK_BYTES + 16384, src + TILE_BYTES, 16384, MB_AL + 16 * buf);
            }
        }
    } else {
        // ---- prologue: normalize this CTA's 128 W rows into SMEM B tile (fp16) ----
        // 16 warps x 8 rows, batched 2 rows/iter (low register footprint)
        #pragma unroll 1
        for (int rb = 0; rb < 4; rb++) {
            int r0 = wid * 8 + rb * 2;
            float4 x[2][4];
            #pragma unroll
            for (int rr = 0; rr < 2; rr++) {
                int c = blockIdx.x * NT + r0 + rr;
                if (c < NCLS) {
                    const float4* s = reinterpret_cast<const float4*>(wraw + (size_t)c * EMB);
                    #pragma unroll
                    for (int q = 0; q < 4; q++) x[rr][q] = s[q * 32 + lane];  // coalesced
                } else {
                    #pragma unroll
                    for (int q = 0; q < 4; q++) x[rr][q] = make_float4(0.f, 0.f, 0.f, 0.f);
                }
            }
            #pragma unroll
            for (int rr = 0; rr < 2; rr++) {
                float ss = dot4(x[rr][0]) + dot4(x[rr][1]) + dot4(x[rr][2]) + dot4(x[rr][3]);
                #pragma unroll
                for (int o = 16; o; o >>= 1) ss += __shfl_xor_sync(0xFFFFFFFFu, ss, o);
                float inv = 1.0f / fmaxf(sqrtf(ss), 1e-12f);
                #pragma unroll
                for (int q = 0; q < 4; q++) {
                    uint32_t lo = pk2h(x[rr][q].x * inv, x[rr][q].y * inv);
                    uint32_t hi = pk2h(x[rr][q].z * inv, x[rr][q].w * inv);
                    uint32_t addr = sw_addr(sb + B_OFF, r0 + rr, q * 128 + lane * 4);
                    asm volatile("st.shared.v2.b32 [%0], {%1, %2};" :: "r"(addr), "r"(lo), "r"(hi) : "memory");
                }
            }
        }
        asm volatile("bar.sync 1, 512;" ::: "memory");   // compute warps only

        // ---- main loop ----
        int wm = wid & 7, wn = wid >> 3;                 // 8 m-slices x 2 n-slices
        int grp = lane >> 3, r8 = lane & 7;
        int a_row = wm * 32 + ((grp & 1) << 3) + r8;     // + i*16 (row in 0..255)
        int a_kof = (grp >> 1) << 3;
        int b_n   = wn * 64 + ((grp >> 1) << 3) + r8;    // + jj*16
        int b_kof = (grp & 1) << 3;
        int qr = lane >> 2, ql = lane & 3;
        int cbase = blockIdx.x * NT + wn * 64 + ql * 2;

        int al_ph[NBUF] = {0, 0};
        #pragma unroll 1
        for (int m = 0; m < 4; m++) {
            uint32_t acch[2][8][2];                      // fp16x2 accumulators, full K
            #pragma unroll
            for (int i = 0; i < 2; i++)
                #pragma unroll
                for (int j = 0; j < 8; j++)
                    acch[i][j][0] = acch[i][j][1] = 0u;

            #pragma unroll 1
            for (int kc = 0; kc < 8; kc++) {
                int g = m * 8 + kc, buf = g & (NBUF - 1);
                MBARRIER_WAIT_PARITY(MB_AL + 16 * buf, al_ph[buf]); al_ph[buf] ^= 1;
                uint32_t abuf = sb + A_OFF + buf * CHUNK_BYTES;

                #pragma unroll
                for (int ks = 0; ks < 4; ks++) {
                    int k = ks * 16;
                    uint32_t a[2][4], b[4][4];
                    ldsm_x4(a[0], chunk_addr(abuf, a_row,      k + a_kof));
                    ldsm_x4(a[1], chunk_addr(abuf, a_row + 16, k + a_kof));
                    #pragma unroll
                    for (int jj = 0; jj < 4; jj++)
                        ldsm_x4(b[jj], sw_addr(sb + B_OFF, b_n + jj * 16, kc * 64 + k + b_kof));
                    if (ks == 3 && lane == 0) MBARRIER_ARRIVE(MB_AC + 16 * buf);
                    #pragma unroll
                    for (int i = 0; i < 2; i++)
                        #pragma unroll
                        for (int j = 0; j < 8; j++)
                            mma_h(acch[i][j], a[i],
                                  b[j >> 1][(j & 1) * 2], b[j >> 1][(j & 1) * 2 + 1]);
                }
            }

            // fused epilogue: exp2(min(v*K, K) - K), label handled exactly by k_fix
            #pragma unroll
            for (int i = 0; i < 2; i++) {
                #pragma unroll
                for (int h = 0; h < 2; h++) {
                    int R = m * 256 + wm * 32 + i * 16 + h * 8 + qr;
                    int lbl = g_labels[R];
                    float sum = 0.0f;
                    #pragma unroll
                    for (int j = 0; j < 8; j++) {
                        float2 p = __half22float2(*reinterpret_cast<__half2*>(&acch[i][j][h]));
                        #pragma unroll
                        for (int e = 0; e < 2; e++) {
                            int c = cbase + j * 8 + e;
                            float v = (e == 0) ? p.x : p.y;
                            float x = ex2f(fminf(v * K_LOG2E, K_LOG2E) - K_LOG2E);
                            if (c != lbl) sum += x;
                        }
                    }
                    sum += __shfl_xor_sync(0xFFFFFFFFu, sum, 1);
                    sum += __shfl_xor_sync(0xFFFFFFFFu, sum, 2);
                    if (ql == 0) atomicAdd(&g_rowsum[R], sum);
                }
            }
        }
    }

    __syncthreads();
    if (tid == 0) {
        for (int i = 0; i < NBUF; i++) { MBAR_INVAL(MB_AL + 16 * i); MBAR_INVAL(MB_AC + 16 * i); }
    }
}

// ===================== final reduction =====================
__global__ void k_final(float* __restrict__ out) {
    __shared__ float sd[BATCH];
    int t = threadIdx.x;
    sd[t] = 64.0f + logf(g_rowsum[t]) - g_target[t];
    __syncthreads();
    for (int s = 512; s > 0; s >>= 1) {
        if (t < s) sd[t] += sd[t + s];
        __syncthreads();
    }
    if (t == 0) out[0] = sd[0] * (1.0f / (float)BATCH);
}

// ===================== launch =====================
extern "C" void kernel_launch(void* const* d_in, const int* in_sizes, int n_in,
                              void* d_out, int out_size) {
    const float* emb = (const float*)d_in[0];
    const float* w   = (const float*)d_in[1];
    const int*   lw  = (const int*)d_in[2];
    float* out = (float*)d_out;

    cudaFuncSetAttribute(k_gemm, cudaFuncAttributeMaxDynamicSharedMemorySize, 197632);

    k_labels<<<1, 256>>>(lw);
    k_prep_a<<<BATCH / 8, 256>>>(emb);
    k_fix<<<BATCH / 8, 256>>>(emb, w);
    k_gemm<<<NTILES, 544, 197632>>>(w);
    k_final<<<1, BATCH>>>(out);
}